// round 13
// baseline (speedup 1.0000x reference)
#include <cuda_runtime.h>
#include <cuda_fp16.h>
#include <cstdint>
#include <cstddef>

#define CB   2
#define CS   4096
#define CL   512
#define CDIM 5120
#define CH   40
#define CHD  128
#define CKV  (2*CDIM)
#define FSCALE 0.08838834764831845f
#define FEPS 1e-6f

// ---------------- static device scratch ----------------
__device__ __half g_wq  [(size_t)CDIM*CDIM];
__device__ __half g_wkv [(size_t)CDIM*CKV];
__device__ __half g_wo  [(size_t)CDIM*CDIM];
__device__ __half g_k   [(size_t)CB*CH*CL*CHD];
__device__ __half g_v   [(size_t)CB*CH*CHD*CL];
__device__ __half g_hid [(size_t)CB*CS*CDIM];
__device__ __half g_ctx [(size_t)CB*CL*CDIM];
__device__ __half g_qs  [(size_t)CB*CS*CDIM];
__device__ __half g_att [(size_t)CB*CS*CDIM];
__device__ float  g_q   [(size_t)CB*CS*CDIM];
__device__ float  g_kv  [(size_t)CB*CL*CKV];

// ---------------- helpers ----------------
__device__ __forceinline__ uint32_t smem_u32(const void* p) {
    uint32_t a;
    asm("{ .reg .u64 t; cvta.to.shared.u64 t, %1; cvt.u32.u64 %0, t; }" : "=r"(a) : "l"(p));
    return a;
}

__device__ __forceinline__ uint32_t pack2h(float x, float y) {
    __half2 h = __floats2half2_rn(x, y);
    return *reinterpret_cast<uint32_t*>(&h);
}

__device__ __forceinline__ void mma16816(float* c, const uint32_t* a, uint32_t b0, uint32_t b1) {
    asm volatile(
        "mma.sync.aligned.m16n8k16.row.col.f32.f16.f16.f32 "
        "{%0,%1,%2,%3},{%4,%5,%6,%7},{%8,%9},{%0,%1,%2,%3};\n"
        : "+f"(c[0]), "+f"(c[1]), "+f"(c[2]), "+f"(c[3])
        : "r"(a[0]), "r"(a[1]), "r"(a[2]), "r"(a[3]), "r"(b0), "r"(b1));
}

#define LDSM_X4(r, addr)                                                              \
    asm volatile("ldmatrix.sync.aligned.m8n8.x4.shared.b16 {%0,%1,%2,%3}, [%4];"      \
                 : "=r"((r)[0]), "=r"((r)[1]), "=r"((r)[2]), "=r"((r)[3]) : "r"(addr))

#define CP_ASYNC16(dst, src) \
    asm volatile("cp.async.ca.shared.global [%0], [%1], 16;\n" :: "r"(dst), "l"(src))
#define CP_COMMIT() asm volatile("cp.async.commit_group;\n" ::: "memory")
#define CP_WAIT0()  asm volatile("cp.async.wait_group 0;\n" ::: "memory")
#define CP_WAIT1()  asm volatile("cp.async.wait_group 1;\n" ::: "memory")

// ---------------- weight transpose to plain fp16:  T[n][k] = W[k][n] ----------------
__global__ void transpose_h(const float* __restrict__ W, __half* __restrict__ T,
                            int K, int N) {
    __shared__ float t[32][33];
    int n0 = blockIdx.x * 32, k0 = blockIdx.y * 32;
    int tx = threadIdx.x, ty = threadIdx.y;
#pragma unroll
    for (int i = 0; i < 32; i += 8)
        t[ty + i][tx] = W[(size_t)(k0 + ty + i) * N + n0 + tx];
    __syncthreads();
#pragma unroll
    for (int i = 0; i < 32; i += 8)
        T[(size_t)(n0 + ty + i) * K + k0 + tx] = __float2half_rn(t[tx][ty + i]);
}

// ---------------- elementwise fp32 -> plain fp16 ----------------
__global__ void tofp16(const float* __restrict__ X, __half* __restrict__ H, size_t n4) {
    size_t i = (size_t)blockIdx.x * 256 + threadIdx.x;
    if (i >= n4) return;
    float4 v = ((const float4*)X)[i];
    ((uint2*)H)[i] = make_uint2(pack2h(v.x, v.y), pack2h(v.z, v.w));
}

// ---------------- RMSNorm in place (fp32) ----------------
__global__ void rmsnorm_rows(float* __restrict__ X, long ld, const float* __restrict__ g) {
    float* row = X + (size_t)blockIdx.x * ld;
    int tid = threadIdx.x;
    float4* r4 = (float4*)row;
    const float4* g4 = (const float4*)g;
    float s = 0.f;
#pragma unroll 5
    for (int i = tid; i < CDIM / 4; i += 256) {
        float4 v = r4[i];
        s += v.x * v.x + v.y * v.y + v.z * v.z + v.w * v.w;
    }
#pragma unroll
    for (int o = 16; o; o >>= 1) s += __shfl_xor_sync(0xffffffffu, s, o);
    __shared__ float ws[8];
    if ((tid & 31) == 0) ws[tid >> 5] = s;
    __syncthreads();
    if (tid == 0) {
        float x = 0.f;
#pragma unroll
        for (int i = 0; i < 8; i++) x += ws[i];
        ws[0] = rsqrtf(x / (float)CDIM + FEPS);
    }
    __syncthreads();
    float rs = ws[0];
#pragma unroll 5
    for (int i = tid; i < CDIM / 4; i += 256) {
        float4 v = r4[i];
        float4 w = g4[i];
        v.x *= rs * w.x; v.y *= rs * w.y; v.z *= rs * w.z; v.w *= rs * w.w;
        r4[i] = v;
    }
}

// ---------------- RMSNorm reading fp32, writing plain fp16 ----------------
__global__ void rmsnorm_h(const float* __restrict__ X, const float* __restrict__ g,
                          __half* __restrict__ H) {
    const float* row = X + (size_t)blockIdx.x * CDIM;
    int tid = threadIdx.x;
    const float4* r4 = (const float4*)row;
    const float4* g4 = (const float4*)g;
    float s = 0.f;
#pragma unroll 5
    for (int i = tid; i < CDIM / 4; i += 256) {
        float4 v = r4[i];
        s += v.x * v.x + v.y * v.y + v.z * v.z + v.w * v.w;
    }
#pragma unroll
    for (int o = 16; o; o >>= 1) s += __shfl_xor_sync(0xffffffffu, s, o);
    __shared__ float ws[8];
    if ((tid & 31) == 0) ws[tid >> 5] = s;
    __syncthreads();
    if (tid == 0) {
        float x = 0.f;
#pragma unroll
        for (int i = 0; i < 8; i++) x += ws[i];
        ws[0] = rsqrtf(x / (float)CDIM + FEPS);
    }
    __syncthreads();
    float rs = ws[0];
    uint2* Hr = (uint2*)(H + (size_t)blockIdx.x * CDIM);
#pragma unroll 5
    for (int i = tid; i < CDIM / 4; i += 256) {
        float4 v = r4[i];
        float4 w = g4[i];
        v.x *= rs * w.x; v.y *= rs * w.y; v.z *= rs * w.z; v.w *= rs * w.w;
        Hr[i] = make_uint2(pack2h(v.x, v.y), pack2h(v.z, v.w));
    }
}

// ---------------- K pack: per-head [ (b*H+h)*L + l ][ d ] fp16 ----------------
__global__ void pack_k(const float* __restrict__ kv, __half* __restrict__ h) {
    size_t i = (size_t)blockIdx.x * 256 + threadIdx.x;
    if (i >= (size_t)CB * CH * CL * CHD) return;
    int d = (int)(i & 127);
    size_t r = i >> 7;
    int ll = (int)(r & 511); r >>= 9;
    int hh = (int)(r % CH);
    int b  = (int)(r / CH);
    h[i] = __float2half_rn(kv[((size_t)(b * CL + ll)) * CKV + hh * CHD + d]);
}

// ---------------- V pack transposed: [ (b*H+h)*D + d ][ l ] fp16 ----------------
__global__ void pack_v(const float* __restrict__ kv, __half* __restrict__ h) {
    size_t i = (size_t)blockIdx.x * 256 + threadIdx.x;
    if (i >= (size_t)CB * CH * CHD * CL) return;
    int ll = (int)(i & 511);
    size_t r = i >> 9;
    int d = (int)(r & 127); r >>= 7;
    int hh = (int)(r % CH);
    int b  = (int)(r / CH);
    h[i] = __float2half_rn(kv[((size_t)(b * CL + ll)) * CKV + CDIM + hh * CHD + d]);
}

// ---------------- fp16 GEMM: 256x128 CTA tile, BK=64, 8 warps 64x64, 2 CTAs/SM ----------------
struct GP {
    const __half* A;  long ldA;
    const __half* B;
    float* C;  long ldC;
    const float* bias;
    int K;
};

#define GPITCH  144
#define TILE_A  (256 * GPITCH)       // 36864
#define TILE_BB (128 * GPITCH)       // 18432
#define BUF_B   (TILE_A + TILE_BB)   // 55296
#define GEMM_SMEM_BYTES (2 * BUF_B)  // 110592

extern __shared__ uint32_t dsm[];

__global__ __launch_bounds__(256, 2) void gemm_tc(GP p) {
    uint32_t sbase = smem_u32(dsm);

    int tid = threadIdx.x, lane = tid & 31, wp = tid >> 5;
    int wm = wp >> 1, wn = wp & 1;    // 4 M-warps x 2 N-warps

    const __half* A = p.A + (size_t)blockIdx.y * 256 * p.ldA;
    const __half* B = p.B + (size_t)blockIdx.x * 128 * p.K;

    float acc[4][8][4];
#pragma unroll
    for (int mi = 0; mi < 4; mi++)
#pragma unroll
        for (int nj = 0; nj < 8; nj++)
#pragma unroll
            for (int q = 0; q < 4; q++) acc[mi][nj][q] = 0.f;

    int nk = p.K / 64;
    int r0 = tid >> 3, c0 = tid & 7;  // row r0+32i, 16B chunk c0 (8 chunks/row)

    int lrowA = (lane & 7) + ((lane >> 3) & 1) * 8;
    int kselA = ((lane >> 4) & 1) * 16;
    int lrowB = (lane & 7) + ((lane >> 4) & 1) * 8;
    int kselB = ((lane >> 3) & 1) * 16;

    auto cpAll = [&](int kt, int buf) {
        uint32_t base = sbase + buf * BUF_B;
        long ka = (long)kt * 64 + c0 * 8;
#pragma unroll
        for (int i = 0; i < 8; i++) {          // A: 256 rows
            int r = r0 + 32 * i;
            CP_ASYNC16(base + (uint32_t)r * GPITCH + c0 * 16,
                       A + (size_t)r * p.ldA + ka);
        }
#pragma unroll
        for (int i = 0; i < 4; i++) {          // B: 128 rows
            int r = r0 + 32 * i;
            CP_ASYNC16(base + TILE_A + (uint32_t)r * GPITCH + c0 * 16,
                       B + (size_t)r * p.K + ka);
        }
    };

    auto compute = [&](int buf) {
        uint32_t aB = sbase + buf * BUF_B;
        uint32_t bB = aB + TILE_A;
        uint32_t aAddr[4], bAddr[4];
#pragma unroll
        for (int mi = 0; mi < 4; mi++)
            aAddr[mi] = aB + (uint32_t)(wm * 64 + mi * 16 + lrowA) * GPITCH + kselA;
#pragma unroll
        for (int njp = 0; njp < 4; njp++)
            bAddr[njp] = bB + (uint32_t)(wn * 64 + njp * 16 + lrowB) * GPITCH + kselB;
#pragma unroll
        for (int kk = 0; kk < 4; kk++) {
            uint32_t ko = kk * 32;
            uint32_t ah[4][4];
#pragma unroll
            for (int mi = 0; mi < 4; mi++) LDSM_X4(ah[mi], aAddr[mi] + ko);
#pragma unroll
            for (int njp = 0; njp < 4; njp++) {
                uint32_t bf[4];
                LDSM_X4(bf, bAddr[njp] + ko);
#pragma unroll
                for (int sub = 0; sub < 2; sub++) {
                    int nj = njp * 2 + sub;
                    uint32_t b0 = bf[sub * 2], b1 = bf[sub * 2 + 1];
#pragma unroll
                    for (int mi = 0; mi < 4; mi++)
                        mma16816(acc[mi][nj], ah[mi], b0, b1);
                }
            }
        }
    };

    cpAll(0, 0);
    CP_COMMIT();
    CP_WAIT0();
    __syncthreads();

    for (int kt = 0; kt < nk; kt++) {
        if (kt + 1 < nk) {
            cpAll(kt + 1, (kt + 1) & 1);
            CP_COMMIT();
        }
        compute(kt & 1);
        CP_WAIT0();
        __syncthreads();
    }

    float* C = p.C + (size_t)blockIdx.y * 256 * p.ldC + (size_t)blockIdx.x * 128;
#pragma unroll
    for (int nj = 0; nj < 8; nj++) {
        int c = wn * 64 + nj * 8 + ((lane & 3) << 1);
        float b0 = 0.f, b1 = 0.f;
        if (p.bias) {
            size_t cg = (size_t)blockIdx.x * 128 + c;
            b0 = p.bias[cg];
            b1 = p.bias[cg + 1];
        }
#pragma unroll
        for (int mi = 0; mi < 4; mi++) {
            int r = wm * 64 + mi * 16 + (lane >> 2);
            *(float2*)&C[(size_t)r * p.ldC + c] =
                make_float2(acc[mi][nj][0] + b0, acc[mi][nj][1] + b1);
            *(float2*)&C[(size_t)(r + 8) * p.ldC + c] =
                make_float2(acc[mi][nj][2] + b0, acc[mi][nj][3] + b1);
        }
    }
}

// ---------------- fused flash attention: all plain fp16 ----------------
#define FPITCH 272
#define FT     (128 * FPITCH)
#define FQ_OFF 0
#define FK_OFF (1 * FT)              // K (P overwrites)
#define FV_OFF (2 * FT)
#define FSTF   ((3 * FT) / 4)
#define F_M    (FSTF)
#define F_L    (FSTF + 128)
#define F_A    (FSTF + 256)
#define F_RMAX (FSTF + 384)
#define F_RSUM (FSTF + 640)
#define FLASH_SMEM (3 * FT + 3584)

__global__ __launch_bounds__(256, 1) void flash_attn() {
    uint32_t sb = smem_u32(dsm);
    float* fs = (float*)dsm;
    int tid = threadIdx.x, lane = tid & 31, wp = tid >> 5;
    int wm = wp >> 1, wn = wp & 1;
    int bh = blockIdx.y, b = bh / CH, hh = bh % CH;
    size_t qrow0 = (size_t)b * CS + (size_t)blockIdx.x * 128;

    const __half* Q = g_qs + qrow0 * CDIM + hh * CHD;
    const __half* K = g_k + (size_t)bh * CL * CHD;
    const __half* V = g_v + (size_t)bh * CHD * CL;

    if (tid < 128) {
        fs[F_M + tid] = -1e30f;
        fs[F_L + tid] = 0.f;
    }

    float O[2][8][4];
#pragma unroll
    for (int mi = 0; mi < 2; mi++)
#pragma unroll
        for (int nj = 0; nj < 8; nj++)
#pragma unroll
            for (int q = 0; q < 4; q++) O[mi][nj][q] = 0.f;

    int lrA = (lane & 7) + ((lane >> 3) & 1) * 8;
    int ksA = ((lane >> 4) & 1) * 16;
    int lrB = (lane & 7) + ((lane >> 4) & 1) * 8;
    int ksB = ((lane >> 3) & 1) * 16;

    auto cpT = [&](uint32_t dst, const __half* src, long stride) {
#pragma unroll
        for (int i = 0; i < 8; i++) {
            int idx = tid + 256 * i;
            int row = idx >> 4, ch = idx & 15;
            CP_ASYNC16(dst + (uint32_t)row * FPITCH + ch * 16,
                       src + (size_t)row * stride + ch * 8);
        }
    };

    cpT(sb + FQ_OFF, Q, CDIM);
    cpT(sb + FK_OFF, K, CHD);
    CP_COMMIT();
    cpT(sb + FV_OFF, V, CL);
    CP_COMMIT();

    uint32_t qA[2];
#pragma unroll
    for (int mi = 0; mi < 2; mi++)
        qA[mi] = sb + (uint32_t)(wm * 32 + mi * 16 + lrA) * FPITCH + ksA;
    uint32_t nB[4];
#pragma unroll
    for (int njp = 0; njp < 4; njp++)
        nB[njp] = (uint32_t)(wn * 64 + njp * 16 + lrB) * FPITCH + ksB;

    for (int j = 0; j < 4; j++) {
        CP_WAIT1();
        __syncthreads();

        float acc[2][8][4];
#pragma unroll
        for (int mi = 0; mi < 2; mi++)
#pragma unroll
            for (int nj = 0; nj < 8; nj++)
#pragma unroll
                for (int q = 0; q < 4; q++) acc[mi][nj][q] = 0.f;

#pragma unroll
        for (int ks = 0; ks < 8; ks++) {
            uint32_t ko = ks * 32;
            uint32_t aq[2][4];
#pragma unroll
            for (int mi = 0; mi < 2; mi++) LDSM_X4(aq[mi], qA[mi] + ko);
#pragma unroll
            for (int njp = 0; njp < 4; njp++) {
                uint32_t bf[4];
                LDSM_X4(bf, sb + FK_OFF + nB[njp] + ko);
#pragma unroll
                for (int sub = 0; sub < 2; sub++) {
                    int nj = njp * 2 + sub;
                    uint32_t b0 = bf[sub * 2], b1 = bf[sub * 2 + 1];
#pragma unroll
                    for (int mi = 0; mi < 2; mi++)
                        mma16816(acc[mi][nj], aq[mi], b0, b1);
                }
            }
        }
#pragma unroll
        for (int mi = 0; mi < 2; mi++)
#pragma unroll
            for (int nj = 0; nj < 8; nj++)
#pragma unroll
                for (int q = 0; q < 4; q++) acc[mi][nj][q] *= FSCALE;

        __syncthreads();

#pragma unroll
        for (int mi = 0; mi < 2; mi++)
#pragma unroll
            for (int h = 0; h < 2; h++) {
                float mx = -1e30f;
#pragma unroll
                for (int nj = 0; nj < 8; nj++)
                    mx = fmaxf(mx, fmaxf(acc[mi][nj][2 * h], acc[mi][nj][2 * h + 1]));
                mx = fmaxf(mx, __shfl_xor_sync(0xffffffffu, mx, 1));
                mx = fmaxf(mx, __shfl_xor_sync(0xffffffffu, mx, 2));
                if ((lane & 3) == 0) {
                    int row = wm * 32 + mi * 16 + (lane >> 2) + h * 8;
                    fs[F_RMAX + row * 2 + wn] = mx;
                }
            }
        __syncthreads();
        if (tid < 128) {
            float mc = fmaxf(fs[F_RMAX + tid * 2], fs[F_RMAX + tid * 2 + 1]);
            float mo = fs[F_M + tid];
            float mn = fmaxf(mo, mc);
            fs[F_M + tid] = mn;
            fs[F_A + tid] = __expf(mo - mn);
        }
        __syncthreads();

#pragma unroll
        for (int mi = 0; mi < 2; mi++)
#pragma unroll
            for (int h = 0; h < 2; h++) {
                int row = wm * 32 + mi * 16 + (lane >> 2) + h * 8;
                float mn = fs[F_M + row];
                float al = fs[F_A + row];
                float s = 0.f;
#pragma unroll
                for (int nj = 0; nj < 8; nj++) {
                    float p0 = __expf(acc[mi][nj][2 * h] - mn);
                    float p1 = __expf(acc[mi][nj][2 * h + 1] - mn);
                    s += p0 + p1;
                    int c = wn * 64 + nj * 8 + 2 * (lane & 3);
                    uint32_t off = ((uint32_t)row * FPITCH + c * 2) >> 2;
                    dsm[(FK_OFF >> 2) + off] = pack2h(p0, p1);
                    O[mi][nj][2 * h] *= al;
                    O[mi][nj][2 * h + 1] *= al;
                }
                s += __shfl_xor_sync(0xffffffffu, s, 1);
                s += __shfl_xor_sync(0xffffffffu, s, 2);
                if ((lane & 3) == 0) fs[F_RSUM + row * 2 + wn] = s;
            }
        __syncthreads();
        if (tid < 128)
            fs[F_L + tid] = fs[F_L + tid] * fs[F_A + tid] +
                            fs[F_RSUM + tid * 2] + fs[F_RSUM + tid * 2 + 1];

        CP_WAIT0();
        __syncthreads();

#pragma unroll
        for (int ks = 0; ks < 8; ks++) {
            uint32_t ko = ks * 32;
            uint32_t ap[2][4];
#pragma unroll
            for (int mi = 0; mi < 2; mi++) {
                uint32_t ro = (uint32_t)(wm * 32 + mi * 16 + lrA) * FPITCH + ksA;
                LDSM_X4(ap[mi], sb + FK_OFF + ro + ko);
            }
#pragma unroll
            for (int njp = 0; njp < 4; njp++) {
                uint32_t bf[4];
                LDSM_X4(bf, sb + FV_OFF + nB[njp] + ko);
#pragma unroll
                for (int sub = 0; sub < 2; sub++) {
                    int nj = njp * 2 + sub;
                    uint32_t b0 = bf[sub * 2], b1 = bf[sub * 2 + 1];
#pragma unroll
                    for (int mi = 0; mi < 2; mi++)
                        mma16816(O[mi][nj], ap[mi], b0, b1);
                }
            }
        }
        __syncthreads();

        if (j < 3) {
            cpT(sb + FK_OFF, K + (size_t)(j + 1) * 128 * CHD, CHD);
            CP_COMMIT();
            cpT(sb + FV_OFF, V + (j + 1) * 128, CL);
            CP_COMMIT();
        }
    }
    __syncthreads();

    __half* Att = g_att + qrow0 * CDIM + hh * CHD;
#pragma unroll
    for (int nj = 0; nj < 8; nj++) {
        int c = wn * 64 + nj * 8 + 2 * (lane & 3);
#pragma unroll
        for (int mi = 0; mi < 2; mi++) {
#pragma unroll
            for (int h = 0; h < 2; h++) {
                int row = wm * 32 + mi * 16 + (lane >> 2) + h * 8;
                float inv = 1.f / fs[F_L + row];
                *(uint32_t*)&Att[(size_t)row * CDIM + c] =
                    pack2h(O[mi][nj][2 * h] * inv, O[mi][nj][2 * h + 1] * inv);
            }
        }
    }
}

// ---------------- host launcher ----------------
extern "C" void kernel_launch(void* const* d_in, const int* in_sizes, int n_in,
                              void* d_out, int out_size) {
    (void)in_sizes; (void)n_in; (void)out_size;
    const float* hid = (const float*)d_in[0];
    const float* ctx = (const float*)d_in[1];
    const float* Wq  = (const float*)d_in[2];
    const float* bq  = (const float*)d_in[3];
    const float* Wkv = (const float*)d_in[4];
    const float* bkv = (const float*)d_in[5];
    const float* gq  = (const float*)d_in[6];
    const float* gk  = (const float*)d_in[7];
    const float* Wo  = (const float*)d_in[8];
    const float* bo  = (const float*)d_in[9];
    float* out = (float*)d_out;

    __half *wq, *wkv, *wo, *hidh, *ctxh, *qs, *att, *kh, *vh;
    float *q, *kv;
    cudaGetSymbolAddress((void**)&wq, g_wq);
    cudaGetSymbolAddress((void**)&wkv, g_wkv);
    cudaGetSymbolAddress((void**)&wo, g_wo);
    cudaGetSymbolAddress((void**)&hidh, g_hid);
    cudaGetSymbolAddress((void**)&ctxh, g_ctx);
    cudaGetSymbolAddress((void**)&qs, g_qs);
    cudaGetSymbolAddress((void**)&att, g_att);
    cudaGetSymbolAddress((void**)&kh, g_k);
    cudaGetSymbolAddress((void**)&vh, g_v);
    cudaGetSymbolAddress((void**)&q, g_q);
    cudaGetSymbolAddress((void**)&kv, g_kv);

    cudaFuncSetAttribute(gemm_tc, cudaFuncAttributeMaxDynamicSharedMemorySize,
                         GEMM_SMEM_BYTES);
    cudaFuncSetAttribute(flash_attn, cudaFuncAttributeMaxDynamicSharedMemorySize,
                         FLASH_SMEM);

    dim3 tb(32, 8);
    transpose_h<<<dim3(CDIM / 32, CDIM / 32), tb>>>(Wq, wq, CDIM, CDIM);
    transpose_h<<<dim3(CKV / 32, CDIM / 32), tb>>>(Wkv, wkv, CDIM, CKV);
    transpose_h<<<dim3(CDIM / 32, CDIM / 32), tb>>>(Wo, wo, CDIM, CDIM);

    {
        size_t n4 = (size_t)CB * CS * CDIM / 4;
        tofp16<<<(unsigned)((n4 + 255) / 256), 256>>>(hid, hidh, n4);
        size_t m4 = (size_t)CB * CL * CDIM / 4;
        tofp16<<<(unsigned)((m4 + 255) / 256), 256>>>(ctx, ctxh, m4);
    }

    GP p{};

    // Q = hidden @ Wq + bq  -> fp32 q   (M = 8192 -> 32 blocks of 256)
    p.A = hidh; p.ldA = CDIM; p.B = wq;
    p.C = q; p.ldC = CDIM; p.bias = bq; p.K = CDIM;
    gemm_tc<<<dim3(CDIM / 128, (CB * CS) / 256), 256, GEMM_SMEM_BYTES>>>(p);

    rmsnorm_h<<<CB * CS, 256>>>(q, gq, qs);

    // KV = context @ Wkv + bkv -> fp32 kv  (M = 1024 -> 4 blocks of 256)
    p.A = ctxh; p.ldA = CDIM; p.B = wkv;
    p.C = kv; p.ldC = CKV; p.bias = bkv; p.K = CDIM;
    gemm_tc<<<dim3(CKV / 128, (CB * CL) / 256), 256, GEMM_SMEM_BYTES>>>(p);

    rmsnorm_rows<<<CB * CL, 256>>>(kv, CKV, gk);

    {
        size_t nK = (size_t)CB * CH * CL * CHD;
        pack_k<<<(unsigned)((nK + 255) / 256), 256>>>(kv, kh);
        pack_v<<<(unsigned)((nK + 255) / 256), 256>>>(kv, vh);
    }

    // fused attention -> plain fp16 att
    flash_attn<<<dim3(CS / 128, CB * CH), 256, FLASH_SMEM>>>();

    // out = att @ Wo + bo
    p.A = att; p.ldA = CDIM; p.B = wo;
    p.C = out; p.ldC = CDIM; p.bias = bo; p.K = CDIM;
    gemm_tc<<<dim3(CDIM / 128, (CB * CS) / 256), 256, GEMM_SMEM_BYTES>>>(p);
}

// round 14
// speedup vs baseline: 3.3450x; 3.3450x over previous
#include <cuda_runtime.h>
#include <cuda_fp16.h>
#include <cstdint>
#include <cstddef>

#define CB   2
#define CS   4096
#define CL   512
#define CDIM 5120
#define CH   40
#define CHD  128
#define CKV  (2*CDIM)
#define FSCALE 0.08838834764831845f
#define FEPS 1e-6f

// ---------------- static device scratch ----------------
__device__ __half g_wq  [(size_t)CDIM*CDIM];
__device__ __half g_wkv [(size_t)CDIM*CKV];
__device__ __half g_wo  [(size_t)CDIM*CDIM];
__device__ __half g_k   [(size_t)CB*CH*CL*CHD];
__device__ __half g_v   [(size_t)CB*CH*CHD*CL];
__device__ __half g_hid [(size_t)CB*CS*CDIM];
__device__ __half g_ctx [(size_t)CB*CL*CDIM];
__device__ __half g_qs  [(size_t)CB*CS*CDIM];
__device__ __half g_att [(size_t)CB*CS*CDIM];
__device__ float  g_q   [(size_t)CB*CS*CDIM];
__device__ float  g_kv  [(size_t)CB*CL*CKV];

// ---------------- helpers ----------------
__device__ __forceinline__ uint32_t smem_u32(const void* p) {
    uint32_t a;
    asm("{ .reg .u64 t; cvta.to.shared.u64 t, %1; cvt.u32.u64 %0, t; }" : "=r"(a) : "l"(p));
    return a;
}

__device__ __forceinline__ uint32_t pack2h(float x, float y) {
    __half2 h = __floats2half2_rn(x, y);
    return *reinterpret_cast<uint32_t*>(&h);
}

__device__ __forceinline__ void mma16816(float* c, const uint32_t* a, uint32_t b0, uint32_t b1) {
    asm volatile(
        "mma.sync.aligned.m16n8k16.row.col.f32.f16.f16.f32 "
        "{%0,%1,%2,%3},{%4,%5,%6,%7},{%8,%9},{%0,%1,%2,%3};\n"
        : "+f"(c[0]), "+f"(c[1]), "+f"(c[2]), "+f"(c[3])
        : "r"(a[0]), "r"(a[1]), "r"(a[2]), "r"(a[3]), "r"(b0), "r"(b1));
}

#define LDSM_X4(r, addr)                                                              \
    asm volatile("ldmatrix.sync.aligned.m8n8.x4.shared.b16 {%0,%1,%2,%3}, [%4];"      \
                 : "=r"((r)[0]), "=r"((r)[1]), "=r"((r)[2]), "=r"((r)[3]) : "r"(addr))

#define CP_ASYNC16(dst, src) \
    asm volatile("cp.async.ca.shared.global [%0], [%1], 16;\n" :: "r"(dst), "l"(src))
#define CP_COMMIT() asm volatile("cp.async.commit_group;\n" ::: "memory")
#define CP_WAIT0()  asm volatile("cp.async.wait_group 0;\n" ::: "memory")
#define CP_WAIT1()  asm volatile("cp.async.wait_group 1;\n" ::: "memory")

// ---------------- weight transpose to plain fp16:  T[n][k] = W[k][n] ----------------
__global__ void transpose_h(const float* __restrict__ W, __half* __restrict__ T,
                            int K, int N) {
    __shared__ float t[32][33];
    int n0 = blockIdx.x * 32, k0 = blockIdx.y * 32;
    int tx = threadIdx.x, ty = threadIdx.y;
#pragma unroll
    for (int i = 0; i < 32; i += 8)
        t[ty + i][tx] = W[(size_t)(k0 + ty + i) * N + n0 + tx];
    __syncthreads();
#pragma unroll
    for (int i = 0; i < 32; i += 8)
        T[(size_t)(n0 + ty + i) * K + k0 + tx] = __float2half_rn(t[tx][ty + i]);
}

// ---------------- elementwise fp32 -> plain fp16 ----------------
__global__ void tofp16(const float* __restrict__ X, __half* __restrict__ H, size_t n4) {
    size_t i = (size_t)blockIdx.x * 256 + threadIdx.x;
    if (i >= n4) return;
    float4 v = ((const float4*)X)[i];
    ((uint2*)H)[i] = make_uint2(pack2h(v.x, v.y), pack2h(v.z, v.w));
}

// ---------------- RMSNorm in place (fp32) ----------------
__global__ void rmsnorm_rows(float* __restrict__ X, long ld, const float* __restrict__ g) {
    float* row = X + (size_t)blockIdx.x * ld;
    int tid = threadIdx.x;
    float4* r4 = (float4*)row;
    const float4* g4 = (const float4*)g;
    float s = 0.f;
#pragma unroll 5
    for (int i = tid; i < CDIM / 4; i += 256) {
        float4 v = r4[i];
        s += v.x * v.x + v.y * v.y + v.z * v.z + v.w * v.w;
    }
#pragma unroll
    for (int o = 16; o; o >>= 1) s += __shfl_xor_sync(0xffffffffu, s, o);
    __shared__ float ws[8];
    if ((tid & 31) == 0) ws[tid >> 5] = s;
    __syncthreads();
    if (tid == 0) {
        float x = 0.f;
#pragma unroll
        for (int i = 0; i < 8; i++) x += ws[i];
        ws[0] = rsqrtf(x / (float)CDIM + FEPS);
    }
    __syncthreads();
    float rs = ws[0];
#pragma unroll 5
    for (int i = tid; i < CDIM / 4; i += 256) {
        float4 v = r4[i];
        float4 w = g4[i];
        v.x *= rs * w.x; v.y *= rs * w.y; v.z *= rs * w.z; v.w *= rs * w.w;
        r4[i] = v;
    }
}

// ---------------- RMSNorm reading fp32, writing plain fp16 ----------------
__global__ void rmsnorm_h(const float* __restrict__ X, const float* __restrict__ g,
                          __half* __restrict__ H) {
    const float* row = X + (size_t)blockIdx.x * CDIM;
    int tid = threadIdx.x;
    const float4* r4 = (const float4*)row;
    const float4* g4 = (const float4*)g;
    float s = 0.f;
#pragma unroll 5
    for (int i = tid; i < CDIM / 4; i += 256) {
        float4 v = r4[i];
        s += v.x * v.x + v.y * v.y + v.z * v.z + v.w * v.w;
    }
#pragma unroll
    for (int o = 16; o; o >>= 1) s += __shfl_xor_sync(0xffffffffu, s, o);
    __shared__ float ws[8];
    if ((tid & 31) == 0) ws[tid >> 5] = s;
    __syncthreads();
    if (tid == 0) {
        float x = 0.f;
#pragma unroll
        for (int i = 0; i < 8; i++) x += ws[i];
        ws[0] = rsqrtf(x / (float)CDIM + FEPS);
    }
    __syncthreads();
    float rs = ws[0];
    uint2* Hr = (uint2*)(H + (size_t)blockIdx.x * CDIM);
#pragma unroll 5
    for (int i = tid; i < CDIM / 4; i += 256) {
        float4 v = r4[i];
        float4 w = g4[i];
        v.x *= rs * w.x; v.y *= rs * w.y; v.z *= rs * w.z; v.w *= rs * w.w;
        Hr[i] = make_uint2(pack2h(v.x, v.y), pack2h(v.z, v.w));
    }
}

// ---------------- fused K+V pack (fp16) ----------------
// first nK indices: K per-head [ (b*H+h)*L + l ][ d ]
// next  nK indices: V transposed [ (b*H+h)*D + d ][ l ]
__global__ void pack_kv(const float* __restrict__ kv, __half* __restrict__ ko,
                        __half* __restrict__ vo) {
    size_t nK = (size_t)CB * CH * CL * CHD;
    size_t i = (size_t)blockIdx.x * 256 + threadIdx.x;
    if (i < nK) {
        int d = (int)(i & 127);
        size_t r = i >> 7;
        int ll = (int)(r & 511); r >>= 9;
        int hh = (int)(r % CH);
        int b  = (int)(r / CH);
        ko[i] = __float2half_rn(kv[((size_t)(b * CL + ll)) * CKV + hh * CHD + d]);
    } else if (i < 2 * nK) {
        size_t j = i - nK;
        int ll = (int)(j & 511);
        size_t r = j >> 9;
        int d = (int)(r & 127); r >>= 7;
        int hh = (int)(r % CH);
        int b  = (int)(r / CH);
        vo[j] = __float2half_rn(kv[((size_t)(b * CL + ll)) * CKV + CDIM + hh * CHD + d]);
    }
}

// ---------------- fp16 GEMM: BK=64, 4 warps 64x64 tiles, 2 CTAs/SM ----------------
struct GP {
    const __half* A;  long ldA;
    const __half* B;
    float* C;  long ldC;
    const float* bias;
    int K;
};

#define GPITCH  144
#define TILE_B  (128 * GPITCH)       // 18432
#define BUF_B   (2 * TILE_B)         // 36864
#define GEMM_SMEM_BYTES (2 * BUF_B)  // 73728

extern __shared__ uint32_t dsm[];

__global__ __launch_bounds__(128, 2) void gemm_tc(GP p) {
    uint32_t sbase = smem_u32(dsm);

    int tid = threadIdx.x, lane = tid & 31, wp = tid >> 5;
    int wm = wp >> 1, wn = wp & 1;

    const __half* A = p.A + (size_t)blockIdx.y * 128 * p.ldA;
    const __half* B = p.B + (size_t)blockIdx.x * 128 * p.K;

    float acc[4][8][4];
#pragma unroll
    for (int mi = 0; mi < 4; mi++)
#pragma unroll
        for (int nj = 0; nj < 8; nj++)
#pragma unroll
            for (int q = 0; q < 4; q++) acc[mi][nj][q] = 0.f;

    int nk = p.K / 64;
    int r0 = tid >> 3, c0 = tid & 7;

    int lrowA = (lane & 7) + ((lane >> 3) & 1) * 8;
    int kselA = ((lane >> 4) & 1) * 16;
    int lrowB = (lane & 7) + ((lane >> 4) & 1) * 8;
    int kselB = ((lane >> 3) & 1) * 16;

    auto cpAll = [&](int kt, int buf) {
        uint32_t base = sbase + buf * BUF_B;
        long ka = (long)kt * 64 + c0 * 8;
#pragma unroll
        for (int i = 0; i < 8; i++) {
            int r = r0 + 16 * i;
            uint32_t d = (uint32_t)r * GPITCH + c0 * 16;
            CP_ASYNC16(base + d,          A + (size_t)r * p.ldA + ka);
            CP_ASYNC16(base + TILE_B + d, B + (size_t)r * p.K + ka);
        }
    };

    auto compute = [&](int buf) {
        uint32_t aB = sbase + buf * BUF_B;
        uint32_t bB = aB + TILE_B;
        uint32_t aAddr[4], bAddr[4];
#pragma unroll
        for (int mi = 0; mi < 4; mi++)
            aAddr[mi] = aB + (uint32_t)(wm * 64 + mi * 16 + lrowA) * GPITCH + kselA;
#pragma unroll
        for (int njp = 0; njp < 4; njp++)
            bAddr[njp] = bB + (uint32_t)(wn * 64 + njp * 16 + lrowB) * GPITCH + kselB;
#pragma unroll
        for (int kk = 0; kk < 4; kk++) {
            uint32_t ko = kk * 32;
            uint32_t ah[4][4];
#pragma unroll
            for (int mi = 0; mi < 4; mi++) LDSM_X4(ah[mi], aAddr[mi] + ko);
#pragma unroll
            for (int njp = 0; njp < 4; njp++) {
                uint32_t bf[4];
                LDSM_X4(bf, bAddr[njp] + ko);
#pragma unroll
                for (int sub = 0; sub < 2; sub++) {
                    int nj = njp * 2 + sub;
                    uint32_t b0 = bf[sub * 2], b1 = bf[sub * 2 + 1];
#pragma unroll
                    for (int mi = 0; mi < 4; mi++)
                        mma16816(acc[mi][nj], ah[mi], b0, b1);
                }
            }
        }
    };

    cpAll(0, 0);
    CP_COMMIT();
    CP_WAIT0();
    __syncthreads();

    for (int kt = 0; kt < nk; kt++) {
        if (kt + 1 < nk) {
            cpAll(kt + 1, (kt + 1) & 1);
            CP_COMMIT();
        }
        compute(kt & 1);
        CP_WAIT0();
        __syncthreads();
    }

    float* C = p.C + (size_t)blockIdx.y * 128 * p.ldC + (size_t)blockIdx.x * 128;
#pragma unroll
    for (int nj = 0; nj < 8; nj++) {
        int c = wn * 64 + nj * 8 + ((lane & 3) << 1);
        float b0 = 0.f, b1 = 0.f;
        if (p.bias) {
            size_t cg = (size_t)blockIdx.x * 128 + c;
            b0 = p.bias[cg];
            b1 = p.bias[cg + 1];
        }
#pragma unroll
        for (int mi = 0; mi < 4; mi++) {
            int r = wm * 64 + mi * 16 + (lane >> 2);
            *(float2*)&C[(size_t)r * p.ldC + c] =
                make_float2(acc[mi][nj][0] + b0, acc[mi][nj][1] + b1);
            *(float2*)&C[(size_t)(r + 8) * p.ldC + c] =
                make_float2(acc[mi][nj][2] + b0, acc[mi][nj][3] + b1);
        }
    }
}

// ---------------- fused flash attention: all plain fp16 ----------------
#define FPITCH 272
#define FT     (128 * FPITCH)
#define FQ_OFF 0
#define FK_OFF (1 * FT)              // K (P overwrites)
#define FV_OFF (2 * FT)
#define FSTF   ((3 * FT) / 4)
#define F_M    (FSTF)
#define F_L    (FSTF + 128)
#define F_A    (FSTF + 256)
#define F_RMAX (FSTF + 384)
#define F_RSUM (FSTF + 640)
#define FLASH_SMEM (3 * FT + 3584)

__global__ __launch_bounds__(256, 1) void flash_attn() {
    uint32_t sb = smem_u32(dsm);
    float* fs = (float*)dsm;
    int tid = threadIdx.x, lane = tid & 31, wp = tid >> 5;
    int wm = wp >> 1, wn = wp & 1;
    int bh = blockIdx.y, b = bh / CH, hh = bh % CH;
    size_t qrow0 = (size_t)b * CS + (size_t)blockIdx.x * 128;

    const __half* Q = g_qs + qrow0 * CDIM + hh * CHD;
    const __half* K = g_k + (size_t)bh * CL * CHD;
    const __half* V = g_v + (size_t)bh * CHD * CL;

    if (tid < 128) {
        fs[F_M + tid] = -1e30f;
        fs[F_L + tid] = 0.f;
    }

    float O[2][8][4];
#pragma unroll
    for (int mi = 0; mi < 2; mi++)
#pragma unroll
        for (int nj = 0; nj < 8; nj++)
#pragma unroll
            for (int q = 0; q < 4; q++) O[mi][nj][q] = 0.f;

    int lrA = (lane & 7) + ((lane >> 3) & 1) * 8;
    int ksA = ((lane >> 4) & 1) * 16;
    int lrB = (lane & 7) + ((lane >> 4) & 1) * 8;
    int ksB = ((lane >> 3) & 1) * 16;

    auto cpT = [&](uint32_t dst, const __half* src, long stride) {
#pragma unroll
        for (int i = 0; i < 8; i++) {
            int idx = tid + 256 * i;
            int row = idx >> 4, ch = idx & 15;
            CP_ASYNC16(dst + (uint32_t)row * FPITCH + ch * 16,
                       src + (size_t)row * stride + ch * 8);
        }
    };

    cpT(sb + FQ_OFF, Q, CDIM);
    cpT(sb + FK_OFF, K, CHD);
    CP_COMMIT();
    cpT(sb + FV_OFF, V, CL);
    CP_COMMIT();

    uint32_t qA[2];
#pragma unroll
    for (int mi = 0; mi < 2; mi++)
        qA[mi] = sb + (uint32_t)(wm * 32 + mi * 16 + lrA) * FPITCH + ksA;
    uint32_t nB[4];
#pragma unroll
    for (int njp = 0; njp < 4; njp++)
        nB[njp] = (uint32_t)(wn * 64 + njp * 16 + lrB) * FPITCH + ksB;

    for (int j = 0; j < 4; j++) {
        CP_WAIT1();
        __syncthreads();

        float acc[2][8][4];
#pragma unroll
        for (int mi = 0; mi < 2; mi++)
#pragma unroll
            for (int nj = 0; nj < 8; nj++)
#pragma unroll
                for (int q = 0; q < 4; q++) acc[mi][nj][q] = 0.f;

#pragma unroll
        for (int ks = 0; ks < 8; ks++) {
            uint32_t ko = ks * 32;
            uint32_t aq[2][4];
#pragma unroll
            for (int mi = 0; mi < 2; mi++) LDSM_X4(aq[mi], qA[mi] + ko);
#pragma unroll
            for (int njp = 0; njp < 4; njp++) {
                uint32_t bf[4];
                LDSM_X4(bf, sb + FK_OFF + nB[njp] + ko);
#pragma unroll
                for (int sub = 0; sub < 2; sub++) {
                    int nj = njp * 2 + sub;
                    uint32_t b0 = bf[sub * 2], b1 = bf[sub * 2 + 1];
#pragma unroll
                    for (int mi = 0; mi < 2; mi++)
                        mma16816(acc[mi][nj], aq[mi], b0, b1);
                }
            }
        }
#pragma unroll
        for (int mi = 0; mi < 2; mi++)
#pragma unroll
            for (int nj = 0; nj < 8; nj++)
#pragma unroll
                for (int q = 0; q < 4; q++) acc[mi][nj][q] *= FSCALE;

        __syncthreads();

#pragma unroll
        for (int mi = 0; mi < 2; mi++)
#pragma unroll
            for (int h = 0; h < 2; h++) {
                float mx = -1e30f;
#pragma unroll
                for (int nj = 0; nj < 8; nj++)
                    mx = fmaxf(mx, fmaxf(acc[mi][nj][2 * h], acc[mi][nj][2 * h + 1]));
                mx = fmaxf(mx, __shfl_xor_sync(0xffffffffu, mx, 1));
                mx = fmaxf(mx, __shfl_xor_sync(0xffffffffu, mx, 2));
                if ((lane & 3) == 0) {
                    int row = wm * 32 + mi * 16 + (lane >> 2) + h * 8;
                    fs[F_RMAX + row * 2 + wn] = mx;
                }
            }
        __syncthreads();
        if (tid < 128) {
            float mc = fmaxf(fs[F_RMAX + tid * 2], fs[F_RMAX + tid * 2 + 1]);
            float mo = fs[F_M + tid];
            float mn = fmaxf(mo, mc);
            fs[F_M + tid] = mn;
            fs[F_A + tid] = __expf(mo - mn);
        }
        __syncthreads();

#pragma unroll
        for (int mi = 0; mi < 2; mi++)
#pragma unroll
            for (int h = 0; h < 2; h++) {
                int row = wm * 32 + mi * 16 + (lane >> 2) + h * 8;
                float mn = fs[F_M + row];
                float al = fs[F_A + row];
                float s = 0.f;
#pragma unroll
                for (int nj = 0; nj < 8; nj++) {
                    float p0 = __expf(acc[mi][nj][2 * h] - mn);
                    float p1 = __expf(acc[mi][nj][2 * h + 1] - mn);
                    s += p0 + p1;
                    int c = wn * 64 + nj * 8 + 2 * (lane & 3);
                    uint32_t off = ((uint32_t)row * FPITCH + c * 2) >> 2;
                    dsm[(FK_OFF >> 2) + off] = pack2h(p0, p1);
                    O[mi][nj][2 * h] *= al;
                    O[mi][nj][2 * h + 1] *= al;
                }
                s += __shfl_xor_sync(0xffffffffu, s, 1);
                s += __shfl_xor_sync(0xffffffffu, s, 2);
                if ((lane & 3) == 0) fs[F_RSUM + row * 2 + wn] = s;
            }
        __syncthreads();
        if (tid < 128)
            fs[F_L + tid] = fs[F_L + tid] * fs[F_A + tid] +
                            fs[F_RSUM + tid * 2] + fs[F_RSUM + tid * 2 + 1];

        CP_WAIT0();
        __syncthreads();

#pragma unroll
        for (int ks = 0; ks < 8; ks++) {
            uint32_t ko = ks * 32;
            uint32_t ap[2][4];
#pragma unroll
            for (int mi = 0; mi < 2; mi++) {
                uint32_t ro = (uint32_t)(wm * 32 + mi * 16 + lrA) * FPITCH + ksA;
                LDSM_X4(ap[mi], sb + FK_OFF + ro + ko);
            }
#pragma unroll
            for (int njp = 0; njp < 4; njp++) {
                uint32_t bf[4];
                LDSM_X4(bf, sb + FV_OFF + nB[njp] + ko);
#pragma unroll
                for (int sub = 0; sub < 2; sub++) {
                    int nj = njp * 2 + sub;
                    uint32_t b0 = bf[sub * 2], b1 = bf[sub * 2 + 1];
#pragma unroll
                    for (int mi = 0; mi < 2; mi++)
                        mma16816(O[mi][nj], ap[mi], b0, b1);
                }
            }
        }
        __syncthreads();

        if (j < 3) {
            cpT(sb + FK_OFF, K + (size_t)(j + 1) * 128 * CHD, CHD);
            CP_COMMIT();
            cpT(sb + FV_OFF, V + (j + 1) * 128, CL);
            CP_COMMIT();
        }
    }
    __syncthreads();

    __half* Att = g_att + qrow0 * CDIM + hh * CHD;
#pragma unroll
    for (int nj = 0; nj < 8; nj++) {
        int c = wn * 64 + nj * 8 + 2 * (lane & 3);
#pragma unroll
        for (int mi = 0; mi < 2; mi++) {
#pragma unroll
            for (int h = 0; h < 2; h++) {
                int row = wm * 32 + mi * 16 + (lane >> 2) + h * 8;
                float inv = 1.f / fs[F_L + row];
                *(uint32_t*)&Att[(size_t)row * CDIM + c] =
                    pack2h(O[mi][nj][2 * h] * inv, O[mi][nj][2 * h + 1] * inv);
            }
        }
    }
}

// ---------------- host launcher (stream fork/join for prep overlap) ----------------
extern "C" void kernel_launch(void* const* d_in, const int* in_sizes, int n_in,
                              void* d_out, int out_size) {
    (void)in_sizes; (void)n_in; (void)out_size;
    const float* hid = (const float*)d_in[0];
    const float* ctx = (const float*)d_in[1];
    const float* Wq  = (const float*)d_in[2];
    const float* bq  = (const float*)d_in[3];
    const float* Wkv = (const float*)d_in[4];
    const float* bkv = (const float*)d_in[5];
    const float* gq  = (const float*)d_in[6];
    const float* gk  = (const float*)d_in[7];
    const float* Wo  = (const float*)d_in[8];
    const float* bo  = (const float*)d_in[9];
    float* out = (float*)d_out;

    __half *wq, *wkv, *wo, *hidh, *ctxh, *qs, *att, *kh, *vh;
    float *q, *kv;
    cudaGetSymbolAddress((void**)&wq, g_wq);
    cudaGetSymbolAddress((void**)&wkv, g_wkv);
    cudaGetSymbolAddress((void**)&wo, g_wo);
    cudaGetSymbolAddress((void**)&hidh, g_hid);
    cudaGetSymbolAddress((void**)&ctxh, g_ctx);
    cudaGetSymbolAddress((void**)&qs, g_qs);
    cudaGetSymbolAddress((void**)&att, g_att);
    cudaGetSymbolAddress((void**)&kh, g_k);
    cudaGetSymbolAddress((void**)&vh, g_v);
    cudaGetSymbolAddress((void**)&q, g_q);
    cudaGetSymbolAddress((void**)&kv, g_kv);

    cudaFuncSetAttribute(gemm_tc, cudaFuncAttributeMaxDynamicSharedMemorySize,
                         GEMM_SMEM_BYTES);
    cudaFuncSetAttribute(flash_attn, cudaFuncAttributeMaxDynamicSharedMemorySize,
                         FLASH_SMEM);

    cudaStream_t side;
    cudaEvent_t evFork, evJoin;
    cudaStreamCreateWithFlags(&side, cudaStreamNonBlocking);
    cudaEventCreateWithFlags(&evFork, cudaEventDisableTiming);
    cudaEventCreateWithFlags(&evJoin, cudaEventDisableTiming);

    dim3 tb(32, 8);

    // fork: side stream handles the KV chain + Wo transpose
    cudaEventRecord(evFork, 0);
    cudaStreamWaitEvent(side, evFork, 0);

    GP p{};

    // ---- side stream: KV path + Wo prep ----
    transpose_h<<<dim3(CKV / 32, CDIM / 32), tb, 0, side>>>(Wkv, wkv, CDIM, CKV);
    {
        size_t m4 = (size_t)CB * CL * CDIM / 4;
        tofp16<<<(unsigned)((m4 + 255) / 256), 256, 0, side>>>(ctx, ctxh, m4);
    }
    p.A = ctxh; p.ldA = CDIM; p.B = wkv;
    p.C = kv; p.ldC = CKV; p.bias = bkv; p.K = CDIM;
    gemm_tc<<<dim3(CKV / 128, (CB * CL) / 128), 128, GEMM_SMEM_BYTES, side>>>(p);
    rmsnorm_rows<<<CB * CL, 256, 0, side>>>(kv, CKV, gk);
    {
        size_t nK2 = 2 * (size_t)CB * CH * CL * CHD;
        pack_kv<<<(unsigned)((nK2 + 255) / 256), 256, 0, side>>>(kv, kh, vh);
    }
    transpose_h<<<dim3(CDIM / 32, CDIM / 32), tb, 0, side>>>(Wo, wo, CDIM, CDIM);
    cudaEventRecord(evJoin, side);

    // ---- main stream: Q path ----
    transpose_h<<<dim3(CDIM / 32, CDIM / 32), tb>>>(Wq, wq, CDIM, CDIM);
    {
        size_t n4 = (size_t)CB * CS * CDIM / 4;
        tofp16<<<(unsigned)((n4 + 255) / 256), 256>>>(hid, hidh, n4);
    }
    p.A = hidh; p.ldA = CDIM; p.B = wq;
    p.C = q; p.ldC = CDIM; p.bias = bq; p.K = CDIM;
    gemm_tc<<<dim3(CDIM / 128, (CB * CS) / 128), 128, GEMM_SMEM_BYTES>>>(p);
    rmsnorm_h<<<CB * CS, 256>>>(q, gq, qs);

    // join: flash needs qs (main) + k/v (side); final gemm needs wo (side)
    cudaStreamWaitEvent(0, evJoin, 0);

    // fused attention -> plain fp16 att
    flash_attn<<<dim3(CS / 128, CB * CH), 256, FLASH_SMEM>>>();

    // out = att @ Wo + bo
    p.A = att; p.ldA = CDIM; p.B = wo;
    p.C = out; p.ldC = CDIM; p.bias = bo; p.K = CDIM;
    gemm_tc<<<dim3(CDIM / 128, (CB * CS) / 128), 128, GEMM_SMEM_BYTES>>>(p);

    cudaEventDestroy(evFork);
    cudaEventDestroy(evJoin);
    cudaStreamDestroy(side);
}